// round 15
// baseline (speedup 1.0000x reference)
#include <cuda_runtime.h>
#include <cuda_bf16.h>
#include <cuda_fp16.h>
#include <cstdint>

#define N_ATOMS   50000
#define N_PAIRS   1600000
#define NF        128
#define N_RBF     20
#define E_TILE    128
#define N_TILES   (N_PAIRS / E_TILE)   // 12500
#define NODE_TILES ((N_ATOMS + 127) / 128)  // 391
#define LOG2F_C   0.69314718055994530942f

typedef unsigned long long u64;

// ---------------- scratch ----------------
__device__ float g_h[N_ATOMS * NF];
__device__ float g_agg[N_ATOMS * NF];

// ---------------- helpers ----------------
__device__ __forceinline__ uint32_t smem_u32(const void* p) {
    uint32_t a;
    asm("{ .reg .u64 t; cvta.to.shared.u64 t, %1; cvt.u32.u64 %0, t; }" : "=r"(a) : "l"(p));
    return a;
}
// fast ssp: softplus(x) - ln2 with polynomial log1p (1 MUFU instead of 2).
// ln(1+e) = P(tau) , tau = 2e-1, degree-5 Chebyshev-derived poly, |err| <= 1.1e-5.
// ssp = max(x,0) + ln(1+e) - ln2  ->  constant folded: k0 - 2*ln2.
__device__ __forceinline__ float sspf(float x) {
    float e = __expf(-fabsf(x));
    float tau = fmaf(2.0f, e, -1.0f);
    float pp = fmaf(tau, 0.00095173f, -0.0034666f);
    pp = fmaf(tau, pp, 0.012278f);
    pp = fmaf(tau, pp, -0.055408f);
    pp = fmaf(tau, pp, 0.333342f);
    pp = fmaf(tau, pp, -0.287689f);   // 1.098605 - 2*ln2
    return fmaxf(x, 0.0f) + pp;
}
__device__ __forceinline__ void red4(float* p, float a, float b, float c, float d) {
    asm volatile("red.global.add.v4.f32 [%0], {%1,%2,%3,%4};"
                 :: "l"(p), "f"(a), "f"(b), "f"(c), "f"(d) : "memory");
}
__device__ __forceinline__ uint32_t pack_f16(float x0, float x1) {
    uint32_t u; asm("cvt.rn.f16x2.f32 %0, %1, %2;" : "=r"(u) : "f"(x1), "f"(x0));
    return u;
}

// ---------------- MMA primitives ----------------
__device__ __forceinline__ void ldmx4(uint32_t r[4], uint32_t addr) {
    asm volatile("ldmatrix.sync.aligned.m8n8.x4.shared.b16 {%0,%1,%2,%3}, [%4];"
                 : "=r"(r[0]), "=r"(r[1]), "=r"(r[2]), "=r"(r[3]) : "r"(addr));
}
__device__ __forceinline__ void mmaf16(float d[4], const uint32_t a[4],
                                       uint32_t b0, uint32_t b1) {
    asm volatile(
        "mma.sync.aligned.m16n8k16.row.col.f32.f16.f16.f32 "
        "{%0,%1,%2,%3}, {%4,%5,%6,%7}, {%8,%9}, {%0,%1,%2,%3};"
        : "+f"(d[0]), "+f"(d[1]), "+f"(d[2]), "+f"(d[3])
        : "r"(a[0]), "r"(a[1]), "r"(a[2]), "r"(a[3]), "r"(b0), "r"(b1));
}

// ---------------- single-pass fp16 HMMA (A[128][136], B[128][136], 272B rows) ----------------
__device__ __forceinline__ void hmma1f(uint32_t aA, uint32_t aB,
                                       int m0, int n0, int lane, float acc[4][2][4]) {
    int lr = lane & 15;
    int lc = (lane >> 4) * 8;
    uint32_t ah[8][4];
    uint32_t rowb = (uint32_t)((m0 + lr) * 272);
#pragma unroll
    for (int k = 0; k < 8; k++) {
        uint32_t cb = (uint32_t)(k * 16 + lc) * 2u;
        ldmx4(ah[k], aA + rowb + cb);
    }
#pragma unroll
    for (int jn = 0; jn < 4; jn++) {
        int np = n0 + jn;
#pragma unroll
        for (int h = 0; h < 2; h++)
#pragma unroll
            for (int j = 0; j < 4; j++) acc[jn][h][j] = 0.f;
        uint32_t nrow = (uint32_t)((np * 16 + lr) * 272);
#pragma unroll
        for (int k = 0; k < 8; k++) {
            uint32_t cb = (uint32_t)(k * 16 + lc) * 2u;
            uint32_t bh[4];
            ldmx4(bh, aB + nrow + cb);
            mmaf16(acc[jn][0], ah[k], bh[0], bh[2]);
            mmaf16(acc[jn][1], ah[k], bh[1], bh[3]);
        }
    }
}

// ================= Kernel 1: persistent h = x@W_in + b_in ; zero agg =================
#define EMB_B    0
#define EMB_A0   34816
#define EMB_A1   69632
#define EMB_BIAS 104448
#define EMB_SMEM (EMB_BIAS + 512)

__global__ __launch_bounds__(512, 1)
void k_embed(const float* __restrict__ x, const float* __restrict__ W_in,
             const float* __restrict__ b_in) {
    extern __shared__ __align__(1024) char sm[];
    float* s_b = reinterpret_cast<float*>(sm + EMB_BIAS);
    int tid = threadIdx.x, wid = tid >> 5, lane = tid & 31;
    int mw = (wid >> 1) * 16, ch = wid & 1;
    int g = lane >> 2, tg = lane & 3;
    uint32_t sbase = smem_u32(sm);

    for (int i = tid; i < 16384; i += 512) {
        int k = i >> 7, n = i & 127;
        *reinterpret_cast<__half*>(sm + EMB_B + (uint32_t)(n * 136 + k) * 2u) =
            __float2half_rn(W_in[i]);
    }
    if (tid < 128) s_b[tid] = b_in[tid];

    int p = 0;
    for (int t = blockIdx.x; t < NODE_TILES; t += gridDim.x) {
        int row0 = t * 128;
        float4 xr[8];
#pragma unroll
        for (int j = 0; j < 8; j++) {
            int i4 = j * 512 + tid;
            int r = i4 >> 5;
            xr[j] = (row0 + r < N_ATOMS)
                ? __ldg(reinterpret_cast<const float4*>(x) + (size_t)(row0 + r) * 32 + (i4 & 31))
                : make_float4(0.f, 0.f, 0.f, 0.f);
        }
        char* aA = sm + (p ? EMB_A1 : EMB_A0);
#pragma unroll
        for (int j = 0; j < 8; j++) {
            int i4 = j * 512 + tid;
            int r = i4 >> 5, q = i4 & 31;
            uint32_t o = (uint32_t)(r * 272 + q * 8);
            *reinterpret_cast<uint32_t*>(aA + o)     = pack_f16(xr[j].x, xr[j].y);
            *reinterpret_cast<uint32_t*>(aA + o + 4) = pack_f16(xr[j].z, xr[j].w);
        }
        __syncthreads();

        float acc[4][2][4];
        hmma1f(sbase + (p ? EMB_A1 : EMB_A0), sbase + EMB_B, mw, ch * 4, lane, acc);

        int r0 = row0 + mw + g, r1 = r0 + 8;
        float2 z2 = make_float2(0.f, 0.f);
#pragma unroll
        for (int jn = 0; jn < 4; jn++) {
            int np = ch * 4 + jn;
            int c0 = np * 16 + 2 * tg, c1 = c0 + 8;
            if (r0 < N_ATOMS) {
                *reinterpret_cast<float2*>(g_h + (size_t)r0 * NF + c0) =
                    make_float2(acc[jn][0][0] + s_b[c0], acc[jn][0][1] + s_b[c0 + 1]);
                *reinterpret_cast<float2*>(g_h + (size_t)r0 * NF + c1) =
                    make_float2(acc[jn][1][0] + s_b[c1], acc[jn][1][1] + s_b[c1 + 1]);
                *reinterpret_cast<float2*>(g_agg + (size_t)r0 * NF + c0) = z2;
                *reinterpret_cast<float2*>(g_agg + (size_t)r0 * NF + c1) = z2;
            }
            if (r1 < N_ATOMS) {
                *reinterpret_cast<float2*>(g_h + (size_t)r1 * NF + c0) =
                    make_float2(acc[jn][0][2] + s_b[c0], acc[jn][0][3] + s_b[c0 + 1]);
                *reinterpret_cast<float2*>(g_h + (size_t)r1 * NF + c1) =
                    make_float2(acc[jn][1][2] + s_b[c1], acc[jn][1][3] + s_b[c1 + 1]);
                *reinterpret_cast<float2*>(g_agg + (size_t)r1 * NF + c0) = z2;
                *reinterpret_cast<float2*>(g_agg + (size_t)r1 * NF + c1) = z2;
            }
        }
        p ^= 1;
    }
}

// ================= Kernel 2: persistent edge kernel (phase-pipelined, all-fp16) =================
#define OFF_A0    0
#define OFF_A1    34816
#define OFF_B     69632
#define OFF_WIJ   104448
#define OFF_F0    172032
#define OFF_F1    181248
#define OFF_WF1   190464
#define OFF_BF1   199680
#define OFF_BF2   200192
#define OFF_RC0   200704
#define OFF_RC1   201216
#define OFF_II0   201728
#define OFF_II1   202240
#define OFF_JJ0   202752
#define OFF_JJ1   203264
#define EDGE_SMEM 203776

// phase B: t = ssp(f@Wf1 + bf1) via fp16 MMA (K=32, 2 steps); fp16 into A tile
__device__ __forceinline__ void edge_phaseB(const char* __restrict__ sF,
                                            const char* __restrict__ sW,
                                            const float* __restrict__ s_bf1,
                                            char* s_A, int mw, int ch, int g, int tg) {
    uint32_t fa[2][4];
    uint32_t r0b = (uint32_t)((mw + g) * 72);
    uint32_t r1b = r0b + 8 * 72;
#pragma unroll
    for (int kk = 0; kk < 2; kk++) {
        uint32_t cb = (uint32_t)((kk * 16 + 2 * tg) * 2);
        fa[kk][0] = *reinterpret_cast<const uint32_t*>(sF + r0b + cb);
        fa[kk][1] = *reinterpret_cast<const uint32_t*>(sF + r1b + cb);
        fa[kk][2] = *reinterpret_cast<const uint32_t*>(sF + r0b + cb + 16);
        fa[kk][3] = *reinterpret_cast<const uint32_t*>(sF + r1b + cb + 16);
    }
#pragma unroll
    for (int np2 = 0; np2 < 8; np2++) {
        int c  = ch * 64 + np2 * 8 + 2 * tg;
        int nb = ch * 64 + np2 * 8 + g;
        float b0v = s_bf1[c], b1v = s_bf1[c + 1];
        float a1[4] = {b0v, b1v, b0v, b1v};
        uint32_t nrow = (uint32_t)(nb * 72);
#pragma unroll
        for (int kk = 0; kk < 2; kk++) {
            uint32_t cb = (uint32_t)((kk * 16 + 2 * tg) * 2);
            uint32_t b0 = *reinterpret_cast<const uint32_t*>(sW + nrow + cb);
            uint32_t b1 = *reinterpret_cast<const uint32_t*>(sW + nrow + cb + 16);
            mmaf16(a1, fa[kk], b0, b1);
        }
        uint32_t off0 = (uint32_t)((mw + g) * 272 + ch * 128 + np2 * 16 + tg * 4);
        uint32_t off1 = off0 + 8 * 272;
        *reinterpret_cast<uint32_t*>(s_A + off0) = pack_f16(sspf(a1[0]), sspf(a1[1]));
        *reinterpret_cast<uint32_t*>(s_A + off1) = pack_f16(sspf(a1[2]), sspf(a1[3]));
    }
}

__global__ __launch_bounds__(512, 1)
void k_edge(const float* __restrict__ f_ij, const float* __restrict__ rcut,
            const float* __restrict__ Wf1, const float* __restrict__ bf1,
            const float* __restrict__ Wf2, const float* __restrict__ bf2,
            const int* __restrict__ idx_i, const int* __restrict__ idx_j) {
    extern __shared__ __align__(1024) char sm[];
    float* s_wij = reinterpret_cast<float*>(sm + OFF_WIJ);
    float* s_bf1 = reinterpret_cast<float*>(sm + OFF_BF1);
    float* s_bf2 = reinterpret_cast<float*>(sm + OFF_BF2);

    int tid = threadIdx.x, wid = tid >> 5, lane = tid & 31;
    int mw = (wid >> 1) * 16, ch = wid & 1;
    int g = lane >> 2, tg = lane & 3;
    uint32_t sbase = smem_u32(sm);

    // ---- one-time init ----
    for (int i = tid; i < 6912; i += 512)
        reinterpret_cast<uint32_t*>(sm + OFF_F0)[i] = 0u;
    __syncthreads();
    for (int i = tid; i < 2560; i += 512) {
        int k = i >> 7, n = i & 127;
        *reinterpret_cast<__half*>(sm + OFF_WF1 + (uint32_t)(n * 36 + k) * 2u) =
            __float2half_rn(Wf1[i]);
    }
    for (int i = tid; i < 16384; i += 512) {
        int k = i >> 7, n = i & 127;
        *reinterpret_cast<__half*>(sm + OFF_B + (uint32_t)(n * 136 + k) * 2u) =
            __float2half_rn(Wf2[i]);
    }
    if (tid < 128) { s_bf1[tid] = bf1[tid]; s_bf2[tid] = bf2[tid]; }
    __syncthreads();

    // ---- prologue: stage tile t0, run its phase B ----
    int t0 = blockIdx.x;
    if (tid < 128) {
        size_t eg = (size_t)(t0 * E_TILE + tid);
        const float4* fp = reinterpret_cast<const float4*>(f_ij + eg * 20);
        float fe[20];
#pragma unroll
        for (int i = 0; i < 5; i++) {
            float4 v = __ldg(fp + i);
            fe[i * 4 + 0] = v.x; fe[i * 4 + 1] = v.y;
            fe[i * 4 + 2] = v.z; fe[i * 4 + 3] = v.w;
        }
#pragma unroll
        for (int c = 0; c < 10; c++)
            *reinterpret_cast<uint32_t*>(sm + OFF_F0 + tid * 72 + c * 4) =
                pack_f16(fe[2 * c], fe[2 * c + 1]);
        reinterpret_cast<float*>(sm + OFF_RC0)[tid] = __ldg(rcut + eg);
        reinterpret_cast<int*>(sm + OFF_II0)[tid]   = __ldg(idx_i + eg);
        reinterpret_cast<int*>(sm + OFF_JJ0)[tid]   = __ldg(idx_j + eg);
    }
    __syncthreads();
    edge_phaseB(sm + OFF_F0, sm + OFF_WF1, s_bf1, sm + OFF_A0, mw, ch, g, tg);

    float4 hv[8];
    int ii_r[8];
    bool have_prev = false;
    int p = 0;

    for (int t = t0; t < N_TILES; t += gridDim.x) {
        int tn = t + gridDim.x;
        bool hn = tn < N_TILES;

        // 1) prefetch edge(t+1) into regs
        float fe[20], rc_v = 0.f; int ii_v = 0, jj_v = 0;
        if (hn && tid < 128) {
            size_t eg = (size_t)(tn * E_TILE + tid);
            const float4* fp = reinterpret_cast<const float4*>(f_ij + eg * 20);
#pragma unroll
            for (int i = 0; i < 5; i++) {
                float4 v = __ldg(fp + i);
                fe[i * 4 + 0] = v.x; fe[i * 4 + 1] = v.y;
                fe[i * 4 + 2] = v.z; fe[i * 4 + 3] = v.w;
            }
            rc_v = __ldg(rcut + eg);
            ii_v = __ldg(idx_i + eg);
            jj_v = __ldg(idx_j + eg);
        }

        // 2) scatter(t-1)
        if (have_prev) {
            int q = lane;
#pragma unroll
            for (int b = 0; b < 8; b++) {
                int e = wid + 16 * b;
                float4 wv = *reinterpret_cast<const float4*>(s_wij + e * 132 + q * 4);
                float* ap = g_agg + (size_t)ii_r[b] * NF + q * 4;
                red4(ap, hv[b].x * wv.x, hv[b].y * wv.y, hv[b].z * wv.z, hv[b].w * wv.w);
            }
        }

        // 3) stage edge(t+1) into buffers[p^1]
        if (hn && tid < 128) {
            char* fN = sm + (p ? OFF_F0 : OFF_F1);
#pragma unroll
            for (int c = 0; c < 10; c++)
                *reinterpret_cast<uint32_t*>(fN + tid * 72 + c * 4) =
                    pack_f16(fe[2 * c], fe[2 * c + 1]);
            reinterpret_cast<float*>(sm + (p ? OFF_RC0 : OFF_RC1))[tid] = rc_v;
            reinterpret_cast<int*>(sm + (p ? OFF_II0 : OFF_II1))[tid]   = ii_v;
            reinterpret_cast<int*>(sm + (p ? OFF_JJ0 : OFF_JJ1))[tid]   = jj_v;
        }
        __syncthreads();   // bar A

        // 4a) phase C(t)
        float acc[4][2][4];
        hmma1f(sbase + (p ? OFF_A1 : OFF_A0), sbase + OFF_B, mw, ch * 4, lane, acc);

        // epilogue: bias + rcut -> s_wij
        {
            const float* s_rc = reinterpret_cast<const float*>(sm + (p ? OFF_RC1 : OFF_RC0));
            int r0 = mw + g, r1 = mw + g + 8;
            float rc0 = s_rc[r0], rc1 = s_rc[r1];
            float* w0 = s_wij + r0 * 132;
            float* w1 = s_wij + r1 * 132;
#pragma unroll
            for (int jn = 0; jn < 4; jn++) {
                int np = ch * 4 + jn;
                int c0 = np * 16 + 2 * tg, c1 = c0 + 8;
                float b00 = s_bf2[c0], b01 = s_bf2[c0 + 1];
                float b10 = s_bf2[c1], b11 = s_bf2[c1 + 1];
                *reinterpret_cast<float2*>(w0 + c0) =
                    make_float2((acc[jn][0][0] + b00) * rc0, (acc[jn][0][1] + b01) * rc0);
                *reinterpret_cast<float2*>(w0 + c1) =
                    make_float2((acc[jn][1][0] + b10) * rc0, (acc[jn][1][1] + b11) * rc0);
                *reinterpret_cast<float2*>(w1 + c0) =
                    make_float2((acc[jn][0][2] + b00) * rc1, (acc[jn][0][3] + b01) * rc1);
                *reinterpret_cast<float2*>(w1 + c1) =
                    make_float2((acc[jn][1][2] + b10) * rc1, (acc[jn][1][3] + b11) * rc1);
            }
        }

        // 4b) phase B(t+1)
        if (hn)
            edge_phaseB(sm + (p ? OFF_F0 : OFF_F1), sm + OFF_WF1, s_bf1,
                        sm + (p ? OFF_A0 : OFF_A1), mw, ch, g, tg);

        // 5) gather(t)
        {
            const int* s_ii = reinterpret_cast<const int*>(sm + (p ? OFF_II1 : OFF_II0));
            const int* s_jj = reinterpret_cast<const int*>(sm + (p ? OFF_JJ1 : OFF_JJ0));
            int q = lane;
            int jj_g[8];
#pragma unroll
            for (int b = 0; b < 8; b++) {
                jj_g[b] = s_jj[wid + 16 * b];
                ii_r[b] = s_ii[wid + 16 * b];
            }
#pragma unroll
            for (int b = 0; b < 8; b++)
                hv[b] = __ldg(reinterpret_cast<const float4*>(g_h) + (size_t)jj_g[b] * 32 + q);
        }
        __syncthreads();   // bar B
        have_prev = true;
        p ^= 1;
    }

    // drain
    if (have_prev) {
        int q = lane;
#pragma unroll
        for (int b = 0; b < 8; b++) {
            int e = wid + 16 * b;
            float4 wv = *reinterpret_cast<const float4*>(s_wij + e * 132 + q * 4);
            float* ap = g_agg + (size_t)ii_r[b] * NF + q * 4;
            red4(ap, hv[b].x * wv.x, hv[b].y * wv.y, hv[b].z * wv.z, hv[b].w * wv.w);
        }
    }
}

// ================= Kernel 3: persistent out = ssp(agg@Wo1+bo1)@Wo2 + bo2 =================
#define OUT_B1   0
#define OUT_B2   34816
#define OUT_A    69632
#define OUT_BIAS1 104448
#define OUT_BIAS2 104960
#define OUT_SMEM 105472

__global__ __launch_bounds__(512, 1)
void k_out(const float* __restrict__ Wo1, const float* __restrict__ bo1,
           const float* __restrict__ Wo2, const float* __restrict__ bo2,
           float* __restrict__ out) {
    extern __shared__ __align__(1024) char sm[];
    float* s_b1 = reinterpret_cast<float*>(sm + OUT_BIAS1);
    float* s_b2 = reinterpret_cast<float*>(sm + OUT_BIAS2);
    int tid = threadIdx.x, wid = tid >> 5, lane = tid & 31;
    int mw = (wid >> 1) * 16, ch = wid & 1;
    int g = lane >> 2, tg = lane & 3;
    uint32_t sbase = smem_u32(sm);

    for (int i = tid; i < 16384; i += 512) {
        int k = i >> 7, n = i & 127;
        uint32_t o = (uint32_t)(n * 136 + k) * 2u;
        *reinterpret_cast<__half*>(sm + OUT_B1 + o) = __float2half_rn(Wo1[i]);
        *reinterpret_cast<__half*>(sm + OUT_B2 + o) = __float2half_rn(Wo2[i]);
    }
    if (tid < 128) { s_b1[tid] = bo1[tid]; s_b2[tid] = bo2[tid]; }

    for (int t = blockIdx.x; t < NODE_TILES; t += gridDim.x) {
        int row0 = t * 128;
        float4 ar[8];
#pragma unroll
        for (int j = 0; j < 8; j++) {
            int i4 = j * 512 + tid;
            int r = i4 >> 5;
            ar[j] = (row0 + r < N_ATOMS)
                ? __ldg(reinterpret_cast<const float4*>(g_agg) + (size_t)(row0 + r) * 32 + (i4 & 31))
                : make_float4(0.f, 0.f, 0.f, 0.f);
        }
#pragma unroll
        for (int j = 0; j < 8; j++) {
            int i4 = j * 512 + tid;
            int r = i4 >> 5, q = i4 & 31;
            uint32_t o = (uint32_t)(r * 272 + q * 8);
            *reinterpret_cast<uint32_t*>(sm + OUT_A + o)     = pack_f16(ar[j].x, ar[j].y);
            *reinterpret_cast<uint32_t*>(sm + OUT_A + o + 4) = pack_f16(ar[j].z, ar[j].w);
        }
        __syncthreads();

        float acc[4][2][4];
        hmma1f(sbase + OUT_A, sbase + OUT_B1, mw, ch * 4, lane, acc);
        __syncthreads();

        {
            int r0 = mw + g, r1 = mw + g + 8;
#pragma unroll
            for (int jn = 0; jn < 4; jn++) {
                int np = ch * 4 + jn;
                int c0 = np * 16 + 2 * tg, c1 = c0 + 8;
                float u00 = sspf(acc[jn][0][0] + s_b1[c0]);
                float u01 = sspf(acc[jn][0][1] + s_b1[c0 + 1]);
                float u10 = sspf(acc[jn][1][0] + s_b1[c1]);
                float u11 = sspf(acc[jn][1][1] + s_b1[c1 + 1]);
                float u02 = sspf(acc[jn][0][2] + s_b1[c0]);
                float u03 = sspf(acc[jn][0][3] + s_b1[c0 + 1]);
                float u12 = sspf(acc[jn][1][2] + s_b1[c1]);
                float u13 = sspf(acc[jn][1][3] + s_b1[c1 + 1]);
                *reinterpret_cast<uint32_t*>(sm + OUT_A + (uint32_t)(r0 * 272 + c0 * 2)) = pack_f16(u00, u01);
                *reinterpret_cast<uint32_t*>(sm + OUT_A + (uint32_t)(r0 * 272 + c1 * 2)) = pack_f16(u10, u11);
                *reinterpret_cast<uint32_t*>(sm + OUT_A + (uint32_t)(r1 * 272 + c0 * 2)) = pack_f16(u02, u03);
                *reinterpret_cast<uint32_t*>(sm + OUT_A + (uint32_t)(r1 * 272 + c1 * 2)) = pack_f16(u12, u13);
            }
        }
        __syncthreads();

        float acc2[4][2][4];
        hmma1f(sbase + OUT_A, sbase + OUT_B2, mw, ch * 4, lane, acc2);

        int r0 = row0 + mw + g, r1 = r0 + 8;
#pragma unroll
        for (int jn = 0; jn < 4; jn++) {
            int np = ch * 4 + jn;
            int c0 = np * 16 + 2 * tg, c1 = c0 + 8;
            if (r0 < N_ATOMS) {
                *reinterpret_cast<float2*>(out + (size_t)r0 * NF + c0) =
                    make_float2(acc2[jn][0][0] + s_b2[c0], acc2[jn][0][1] + s_b2[c0 + 1]);
                *reinterpret_cast<float2*>(out + (size_t)r0 * NF + c1) =
                    make_float2(acc2[jn][1][0] + s_b2[c1], acc2[jn][1][1] + s_b2[c1 + 1]);
            }
            if (r1 < N_ATOMS) {
                *reinterpret_cast<float2*>(out + (size_t)r1 * NF + c0) =
                    make_float2(acc2[jn][0][2] + s_b2[c0], acc2[jn][0][3] + s_b2[c0 + 1]);
                *reinterpret_cast<float2*>(out + (size_t)r1 * NF + c1) =
                    make_float2(acc2[jn][1][2] + s_b2[c1], acc2[jn][1][3] + s_b2[c1 + 1]);
            }
        }
        __syncthreads();
    }
}

// ================= launch =================
extern "C" void kernel_launch(void* const* d_in, const int* in_sizes, int n_in,
                              void* d_out, int out_size) {
    const float* x     = (const float*)d_in[0];
    const float* f_ij  = (const float*)d_in[1];
    const float* rcut  = (const float*)d_in[2];
    const float* W_in  = (const float*)d_in[3];
    const float* b_in  = (const float*)d_in[4];
    const float* Wf1   = (const float*)d_in[5];
    const float* bf1   = (const float*)d_in[6];
    const float* Wf2   = (const float*)d_in[7];
    const float* bf2   = (const float*)d_in[8];
    const float* Wo1   = (const float*)d_in[9];
    const float* bo1   = (const float*)d_in[10];
    const float* Wo2   = (const float*)d_in[11];
    const float* bo2   = (const float*)d_in[12];
    const int*   idx_i = (const int*)d_in[13];
    const int*   idx_j = (const int*)d_in[14];
    float* out = (float*)d_out;

    cudaFuncSetAttribute(k_embed, cudaFuncAttributeMaxDynamicSharedMemorySize, EMB_SMEM);
    cudaFuncSetAttribute(k_edge,  cudaFuncAttributeMaxDynamicSharedMemorySize, EDGE_SMEM);
    cudaFuncSetAttribute(k_out,   cudaFuncAttributeMaxDynamicSharedMemorySize, OUT_SMEM);

    int nsm = 148;
    cudaDeviceGetAttribute(&nsm, cudaDevAttrMultiProcessorCount, 0);

    k_embed<<<nsm, 512, EMB_SMEM>>>(x, W_in, b_in);
    k_edge<<<nsm, 512, EDGE_SMEM>>>(f_ij, rcut, Wf1, bf1, Wf2, bf2, idx_i, idx_j);
    k_out<<<nsm, 512, OUT_SMEM>>>(Wo1, bo1, Wo2, bo2, out);
}

// round 16
// speedup vs baseline: 1.0646x; 1.0646x over previous
#include <cuda_runtime.h>
#include <cuda_bf16.h>
#include <cuda_fp16.h>
#include <cstdint>

#define N_ATOMS   50000
#define N_PAIRS   1600000
#define NF        128
#define N_RBF     20
#define E_TILE    128
#define N_TILES   (N_PAIRS / E_TILE)   // 12500
#define NODE_TILES ((N_ATOMS + 127) / 128)  // 391
#define LOG2F_C   0.69314718055994530942f

typedef unsigned long long u64;

// ---------------- scratch ----------------
__device__ __half g_h[N_ATOMS * NF];     // fp16 node features
__device__ float  g_agg[N_ATOMS * NF];

// ---------------- helpers ----------------
__device__ __forceinline__ uint32_t smem_u32(const void* p) {
    uint32_t a;
    asm("{ .reg .u64 t; cvta.to.shared.u64 t, %1; cvt.u32.u64 %0, t; }" : "=r"(a) : "l"(p));
    return a;
}
__device__ __forceinline__ float sspf(float x) {
    float e = __expf(-fabsf(x));
    return fmaxf(x, 0.0f) + __logf(1.0f + e) - LOG2F_C;
}
__device__ __forceinline__ void red4(float* p, float a, float b, float c, float d) {
    asm volatile("red.global.add.v4.f32 [%0], {%1,%2,%3,%4};"
                 :: "l"(p), "f"(a), "f"(b), "f"(c), "f"(d) : "memory");
}
__device__ __forceinline__ uint32_t pack_f16(float x0, float x1) {
    uint32_t u; asm("cvt.rn.f16x2.f32 %0, %1, %2;" : "=r"(u) : "f"(x1), "f"(x0));
    return u;
}

// ---------------- MMA primitives ----------------
__device__ __forceinline__ void ldmx4(uint32_t r[4], uint32_t addr) {
    asm volatile("ldmatrix.sync.aligned.m8n8.x4.shared.b16 {%0,%1,%2,%3}, [%4];"
                 : "=r"(r[0]), "=r"(r[1]), "=r"(r[2]), "=r"(r[3]) : "r"(addr));
}
__device__ __forceinline__ void mmaf16(float d[4], const uint32_t a[4],
                                       uint32_t b0, uint32_t b1) {
    asm volatile(
        "mma.sync.aligned.m16n8k16.row.col.f32.f16.f16.f32 "
        "{%0,%1,%2,%3}, {%4,%5,%6,%7}, {%8,%9}, {%0,%1,%2,%3};"
        : "+f"(d[0]), "+f"(d[1]), "+f"(d[2]), "+f"(d[3])
        : "r"(a[0]), "r"(a[1]), "r"(a[2]), "r"(a[3]), "r"(b0), "r"(b1));
}

// ---------------- single-pass fp16 HMMA (A[128][136], B[128][136], 272B rows) ----------------
__device__ __forceinline__ void hmma1f(uint32_t aA, uint32_t aB,
                                       int m0, int n0, int lane, float acc[4][2][4]) {
    int lr = lane & 15;
    int lc = (lane >> 4) * 8;
    uint32_t ah[8][4];
    uint32_t rowb = (uint32_t)((m0 + lr) * 272);
#pragma unroll
    for (int k = 0; k < 8; k++) {
        uint32_t cb = (uint32_t)(k * 16 + lc) * 2u;
        ldmx4(ah[k], aA + rowb + cb);
    }
#pragma unroll
    for (int jn = 0; jn < 4; jn++) {
        int np = n0 + jn;
#pragma unroll
        for (int h = 0; h < 2; h++)
#pragma unroll
            for (int j = 0; j < 4; j++) acc[jn][h][j] = 0.f;
        uint32_t nrow = (uint32_t)((np * 16 + lr) * 272);
#pragma unroll
        for (int k = 0; k < 8; k++) {
            uint32_t cb = (uint32_t)(k * 16 + lc) * 2u;
            uint32_t bh[4];
            ldmx4(bh, aB + nrow + cb);
            mmaf16(acc[jn][0], ah[k], bh[0], bh[2]);
            mmaf16(acc[jn][1], ah[k], bh[1], bh[3]);
        }
    }
}

// ================= Kernel 1: persistent h = x@W_in + b_in (fp16 out) =================
#define EMB_B    0
#define EMB_A0   34816
#define EMB_A1   69632
#define EMB_BIAS 104448
#define EMB_SMEM (EMB_BIAS + 512)

__global__ __launch_bounds__(512, 1)
void k_embed(const float* __restrict__ x, const float* __restrict__ W_in,
             const float* __restrict__ b_in) {
    extern __shared__ __align__(1024) char sm[];
    float* s_b = reinterpret_cast<float*>(sm + EMB_BIAS);
    int tid = threadIdx.x, wid = tid >> 5, lane = tid & 31;
    int mw = (wid >> 1) * 16, ch = wid & 1;
    int g = lane >> 2, tg = lane & 3;
    uint32_t sbase = smem_u32(sm);

    for (int i = tid; i < 16384; i += 512) {
        int k = i >> 7, n = i & 127;
        *reinterpret_cast<__half*>(sm + EMB_B + (uint32_t)(n * 136 + k) * 2u) =
            __float2half_rn(W_in[i]);
    }
    if (tid < 128) s_b[tid] = b_in[tid];

    int p = 0;
    for (int t = blockIdx.x; t < NODE_TILES; t += gridDim.x) {
        int row0 = t * 128;
        float4 xr[8];
#pragma unroll
        for (int j = 0; j < 8; j++) {
            int i4 = j * 512 + tid;
            int r = i4 >> 5;
            xr[j] = (row0 + r < N_ATOMS)
                ? __ldg(reinterpret_cast<const float4*>(x) + (size_t)(row0 + r) * 32 + (i4 & 31))
                : make_float4(0.f, 0.f, 0.f, 0.f);
        }
        char* aA = sm + (p ? EMB_A1 : EMB_A0);
#pragma unroll
        for (int j = 0; j < 8; j++) {
            int i4 = j * 512 + tid;
            int r = i4 >> 5, q = i4 & 31;
            uint32_t o = (uint32_t)(r * 272 + q * 8);
            *reinterpret_cast<uint32_t*>(aA + o)     = pack_f16(xr[j].x, xr[j].y);
            *reinterpret_cast<uint32_t*>(aA + o + 4) = pack_f16(xr[j].z, xr[j].w);
        }
        __syncthreads();

        float acc[4][2][4];
        hmma1f(sbase + (p ? EMB_A1 : EMB_A0), sbase + EMB_B, mw, ch * 4, lane, acc);

        int r0 = row0 + mw + g, r1 = r0 + 8;
#pragma unroll
        for (int jn = 0; jn < 4; jn++) {
            int np = ch * 4 + jn;
            int c0 = np * 16 + 2 * tg, c1 = c0 + 8;
            if (r0 < N_ATOMS) {
                *reinterpret_cast<uint32_t*>(reinterpret_cast<char*>(g_h) + ((size_t)r0 * NF + c0) * 2) =
                    pack_f16(acc[jn][0][0] + s_b[c0], acc[jn][0][1] + s_b[c0 + 1]);
                *reinterpret_cast<uint32_t*>(reinterpret_cast<char*>(g_h) + ((size_t)r0 * NF + c1) * 2) =
                    pack_f16(acc[jn][1][0] + s_b[c1], acc[jn][1][1] + s_b[c1 + 1]);
            }
            if (r1 < N_ATOMS) {
                *reinterpret_cast<uint32_t*>(reinterpret_cast<char*>(g_h) + ((size_t)r1 * NF + c0) * 2) =
                    pack_f16(acc[jn][0][2] + s_b[c0], acc[jn][0][3] + s_b[c0 + 1]);
                *reinterpret_cast<uint32_t*>(reinterpret_cast<char*>(g_h) + ((size_t)r1 * NF + c1) * 2) =
                    pack_f16(acc[jn][1][2] + s_b[c1], acc[jn][1][3] + s_b[c1 + 1]);
            }
        }
        p ^= 1;
    }
}

// ================= Kernel 2: persistent edge kernel (phase-pipelined, all-fp16) =================
#define OFF_A0    0
#define OFF_A1    34816
#define OFF_B     69632
#define OFF_WIJ   104448
#define OFF_F0    172032
#define OFF_F1    181248
#define OFF_WF1   190464
#define OFF_BF1   199680
#define OFF_BF2   200192
#define OFF_RC0   200704
#define OFF_RC1   201216
#define OFF_II0   201728
#define OFF_II1   202240
#define OFF_JJ0   202752
#define OFF_JJ1   203264
#define EDGE_SMEM 203776

// phase B: t = ssp(f@Wf1 + bf1) via fp16 MMA (K=32, 2 steps); fp16 into A tile
__device__ __forceinline__ void edge_phaseB(const char* __restrict__ sF,
                                            const char* __restrict__ sW,
                                            const float* __restrict__ s_bf1,
                                            char* s_A, int mw, int ch, int g, int tg) {
    uint32_t fa[2][4];
    uint32_t r0b = (uint32_t)((mw + g) * 72);
    uint32_t r1b = r0b + 8 * 72;
#pragma unroll
    for (int kk = 0; kk < 2; kk++) {
        uint32_t cb = (uint32_t)((kk * 16 + 2 * tg) * 2);
        fa[kk][0] = *reinterpret_cast<const uint32_t*>(sF + r0b + cb);
        fa[kk][1] = *reinterpret_cast<const uint32_t*>(sF + r1b + cb);
        fa[kk][2] = *reinterpret_cast<const uint32_t*>(sF + r0b + cb + 16);
        fa[kk][3] = *reinterpret_cast<const uint32_t*>(sF + r1b + cb + 16);
    }
#pragma unroll
    for (int np2 = 0; np2 < 8; np2++) {
        int c  = ch * 64 + np2 * 8 + 2 * tg;
        int nb = ch * 64 + np2 * 8 + g;
        float b0v = s_bf1[c], b1v = s_bf1[c + 1];
        float a1[4] = {b0v, b1v, b0v, b1v};
        uint32_t nrow = (uint32_t)(nb * 72);
#pragma unroll
        for (int kk = 0; kk < 2; kk++) {
            uint32_t cb = (uint32_t)((kk * 16 + 2 * tg) * 2);
            uint32_t b0 = *reinterpret_cast<const uint32_t*>(sW + nrow + cb);
            uint32_t b1 = *reinterpret_cast<const uint32_t*>(sW + nrow + cb + 16);
            mmaf16(a1, fa[kk], b0, b1);
        }
        uint32_t off0 = (uint32_t)((mw + g) * 272 + ch * 128 + np2 * 16 + tg * 4);
        uint32_t off1 = off0 + 8 * 272;
        *reinterpret_cast<uint32_t*>(s_A + off0) = pack_f16(sspf(a1[0]), sspf(a1[1]));
        *reinterpret_cast<uint32_t*>(s_A + off1) = pack_f16(sspf(a1[2]), sspf(a1[3]));
    }
}

__global__ __launch_bounds__(512, 1)
void k_edge(const float* __restrict__ f_ij, const float* __restrict__ rcut,
            const float* __restrict__ Wf1, const float* __restrict__ bf1,
            const float* __restrict__ Wf2, const float* __restrict__ bf2,
            const int* __restrict__ idx_i, const int* __restrict__ idx_j) {
    extern __shared__ __align__(1024) char sm[];
    float* s_wij = reinterpret_cast<float*>(sm + OFF_WIJ);
    float* s_bf1 = reinterpret_cast<float*>(sm + OFF_BF1);
    float* s_bf2 = reinterpret_cast<float*>(sm + OFF_BF2);

    int tid = threadIdx.x, wid = tid >> 5, lane = tid & 31;
    int mw = (wid >> 1) * 16, ch = wid & 1;
    int g = lane >> 2, tg = lane & 3;
    uint32_t sbase = smem_u32(sm);

    // ---- one-time init ----
    for (int i = tid; i < 6912; i += 512)
        reinterpret_cast<uint32_t*>(sm + OFF_F0)[i] = 0u;
    __syncthreads();
    for (int i = tid; i < 2560; i += 512) {
        int k = i >> 7, n = i & 127;
        *reinterpret_cast<__half*>(sm + OFF_WF1 + (uint32_t)(n * 36 + k) * 2u) =
            __float2half_rn(Wf1[i]);
    }
    for (int i = tid; i < 16384; i += 512) {
        int k = i >> 7, n = i & 127;
        *reinterpret_cast<__half*>(sm + OFF_B + (uint32_t)(n * 136 + k) * 2u) =
            __float2half_rn(Wf2[i]);
    }
    if (tid < 128) { s_bf1[tid] = bf1[tid]; s_bf2[tid] = bf2[tid]; }
    __syncthreads();

    // ---- prologue: stage tile t0, run its phase B ----
    int t0 = blockIdx.x;
    if (tid < 128) {
        size_t eg = (size_t)(t0 * E_TILE + tid);
        const float4* fp = reinterpret_cast<const float4*>(f_ij + eg * 20);
        float fe[20];
#pragma unroll
        for (int i = 0; i < 5; i++) {
            float4 v = __ldg(fp + i);
            fe[i * 4 + 0] = v.x; fe[i * 4 + 1] = v.y;
            fe[i * 4 + 2] = v.z; fe[i * 4 + 3] = v.w;
        }
#pragma unroll
        for (int c = 0; c < 10; c++)
            *reinterpret_cast<uint32_t*>(sm + OFF_F0 + tid * 72 + c * 4) =
                pack_f16(fe[2 * c], fe[2 * c + 1]);
        reinterpret_cast<float*>(sm + OFF_RC0)[tid] = __ldg(rcut + eg);
        reinterpret_cast<int*>(sm + OFF_II0)[tid]   = __ldg(idx_i + eg);
        reinterpret_cast<int*>(sm + OFF_JJ0)[tid]   = __ldg(idx_j + eg);
    }
    __syncthreads();
    edge_phaseB(sm + OFF_F0, sm + OFF_WF1, s_bf1, sm + OFF_A0, mw, ch, g, tg);

    uint2 hv[8];       // fp16x4 gathered h rows
    int ii_r[8];
    bool have_prev = false;
    int p = 0;

    for (int t = t0; t < N_TILES; t += gridDim.x) {
        int tn = t + gridDim.x;
        bool hn = tn < N_TILES;

        // 1) prefetch edge(t+1) into regs
        float fe[20], rc_v = 0.f; int ii_v = 0, jj_v = 0;
        if (hn && tid < 128) {
            size_t eg = (size_t)(tn * E_TILE + tid);
            const float4* fp = reinterpret_cast<const float4*>(f_ij + eg * 20);
#pragma unroll
            for (int i = 0; i < 5; i++) {
                float4 v = __ldg(fp + i);
                fe[i * 4 + 0] = v.x; fe[i * 4 + 1] = v.y;
                fe[i * 4 + 2] = v.z; fe[i * 4 + 3] = v.w;
            }
            rc_v = __ldg(rcut + eg);
            ii_v = __ldg(idx_i + eg);
            jj_v = __ldg(idx_j + eg);
        }

        // 2) scatter(t-1): overlaps prefetch LDG latency
        if (have_prev) {
            int q = lane;
#pragma unroll
            for (int b = 0; b < 8; b++) {
                int e = wid + 16 * b;
                float4 wv = *reinterpret_cast<const float4*>(s_wij + e * 132 + q * 4);
                __half2 h01 = *reinterpret_cast<const __half2*>(&hv[b].x);
                __half2 h23 = *reinterpret_cast<const __half2*>(&hv[b].y);
                float2 f01 = __half22float2(h01);
                float2 f23 = __half22float2(h23);
                float* ap = g_agg + (size_t)ii_r[b] * NF + q * 4;
                red4(ap, f01.x * wv.x, f01.y * wv.y, f23.x * wv.z, f23.y * wv.w);
            }
        }

        // 3) stage edge(t+1) into buffers[p^1]
        if (hn && tid < 128) {
            char* fN = sm + (p ? OFF_F0 : OFF_F1);
#pragma unroll
            for (int c = 0; c < 10; c++)
                *reinterpret_cast<uint32_t*>(fN + tid * 72 + c * 4) =
                    pack_f16(fe[2 * c], fe[2 * c + 1]);
            reinterpret_cast<float*>(sm + (p ? OFF_RC0 : OFF_RC1))[tid] = rc_v;
            reinterpret_cast<int*>(sm + (p ? OFF_II0 : OFF_II1))[tid]   = ii_v;
            reinterpret_cast<int*>(sm + (p ? OFF_JJ0 : OFF_JJ1))[tid]   = jj_v;
        }
        __syncthreads();   // bar A

        // 4a) phase C(t)
        float acc[4][2][4];
        hmma1f(sbase + (p ? OFF_A1 : OFF_A0), sbase + OFF_B, mw, ch * 4, lane, acc);

        // epilogue: bias + rcut -> s_wij
        {
            const float* s_rc = reinterpret_cast<const float*>(sm + (p ? OFF_RC1 : OFF_RC0));
            int r0 = mw + g, r1 = mw + g + 8;
            float rc0 = s_rc[r0], rc1 = s_rc[r1];
            float* w0 = s_wij + r0 * 132;
            float* w1 = s_wij + r1 * 132;
#pragma unroll
            for (int jn = 0; jn < 4; jn++) {
                int np = ch * 4 + jn;
                int c0 = np * 16 + 2 * tg, c1 = c0 + 8;
                float b00 = s_bf2[c0], b01 = s_bf2[c0 + 1];
                float b10 = s_bf2[c1], b11 = s_bf2[c1 + 1];
                *reinterpret_cast<float2*>(w0 + c0) =
                    make_float2((acc[jn][0][0] + b00) * rc0, (acc[jn][0][1] + b01) * rc0);
                *reinterpret_cast<float2*>(w0 + c1) =
                    make_float2((acc[jn][1][0] + b10) * rc0, (acc[jn][1][1] + b11) * rc0);
                *reinterpret_cast<float2*>(w1 + c0) =
                    make_float2((acc[jn][0][2] + b00) * rc1, (acc[jn][0][3] + b01) * rc1);
                *reinterpret_cast<float2*>(w1 + c1) =
                    make_float2((acc[jn][1][2] + b10) * rc1, (acc[jn][1][3] + b11) * rc1);
            }
        }

        // 4b) phase B(t+1)
        if (hn)
            edge_phaseB(sm + (p ? OFF_F0 : OFF_F1), sm + OFF_WF1, s_bf1,
                        sm + (p ? OFF_A0 : OFF_A1), mw, ch, g, tg);

        // 5) gather(t): fp16 rows, warp-contiguous
        {
            const int* s_ii = reinterpret_cast<const int*>(sm + (p ? OFF_II1 : OFF_II0));
            const int* s_jj = reinterpret_cast<const int*>(sm + (p ? OFF_JJ1 : OFF_JJ0));
            int q = lane;
            int jj_g[8];
#pragma unroll
            for (int b = 0; b < 8; b++) {
                jj_g[b] = s_jj[wid + 16 * b];
                ii_r[b] = s_ii[wid + 16 * b];
            }
#pragma unroll
            for (int b = 0; b < 8; b++)
                hv[b] = __ldg(reinterpret_cast<const uint2*>(g_h) + (size_t)jj_g[b] * 32 + q);
        }
        __syncthreads();   // bar B
        have_prev = true;
        p ^= 1;
    }

    // drain
    if (have_prev) {
        int q = lane;
#pragma unroll
        for (int b = 0; b < 8; b++) {
            int e = wid + 16 * b;
            float4 wv = *reinterpret_cast<const float4*>(s_wij + e * 132 + q * 4);
            __half2 h01 = *reinterpret_cast<const __half2*>(&hv[b].x);
            __half2 h23 = *reinterpret_cast<const __half2*>(&hv[b].y);
            float2 f01 = __half22float2(h01);
            float2 f23 = __half22float2(h23);
            float* ap = g_agg + (size_t)ii_r[b] * NF + q * 4;
            red4(ap, f01.x * wv.x, f01.y * wv.y, f23.x * wv.z, f23.y * wv.w);
        }
    }
}

// ================= Kernel 3: persistent out = ssp(agg@Wo1+bo1)@Wo2 + bo2 =================
#define OUT_B1   0
#define OUT_B2   34816
#define OUT_A    69632
#define OUT_BIAS1 104448
#define OUT_BIAS2 104960
#define OUT_SMEM 105472

__global__ __launch_bounds__(512, 1)
void k_out(const float* __restrict__ Wo1, const float* __restrict__ bo1,
           const float* __restrict__ Wo2, const float* __restrict__ bo2,
           float* __restrict__ out) {
    extern __shared__ __align__(1024) char sm[];
    float* s_b1 = reinterpret_cast<float*>(sm + OUT_BIAS1);
    float* s_b2 = reinterpret_cast<float*>(sm + OUT_BIAS2);
    int tid = threadIdx.x, wid = tid >> 5, lane = tid & 31;
    int mw = (wid >> 1) * 16, ch = wid & 1;
    int g = lane >> 2, tg = lane & 3;
    uint32_t sbase = smem_u32(sm);

    for (int i = tid; i < 16384; i += 512) {
        int k = i >> 7, n = i & 127;
        uint32_t o = (uint32_t)(n * 136 + k) * 2u;
        *reinterpret_cast<__half*>(sm + OUT_B1 + o) = __float2half_rn(Wo1[i]);
        *reinterpret_cast<__half*>(sm + OUT_B2 + o) = __float2half_rn(Wo2[i]);
    }
    if (tid < 128) { s_b1[tid] = bo1[tid]; s_b2[tid] = bo2[tid]; }

    for (int t = blockIdx.x; t < NODE_TILES; t += gridDim.x) {
        int row0 = t * 128;
        float4 ar[8];
#pragma unroll
        for (int j = 0; j < 8; j++) {
            int i4 = j * 512 + tid;
            int r = i4 >> 5;
            ar[j] = (row0 + r < N_ATOMS)
                ? __ldg(reinterpret_cast<const float4*>(g_agg) + (size_t)(row0 + r) * 32 + (i4 & 31))
                : make_float4(0.f, 0.f, 0.f, 0.f);
        }
#pragma unroll
        for (int j = 0; j < 8; j++) {
            int i4 = j * 512 + tid;
            int r = i4 >> 5, q = i4 & 31;
            uint32_t o = (uint32_t)(r * 272 + q * 8);
            *reinterpret_cast<uint32_t*>(sm + OUT_A + o)     = pack_f16(ar[j].x, ar[j].y);
            *reinterpret_cast<uint32_t*>(sm + OUT_A + o + 4) = pack_f16(ar[j].z, ar[j].w);
        }
        __syncthreads();

        float acc[4][2][4];
        hmma1f(sbase + OUT_A, sbase + OUT_B1, mw, ch * 4, lane, acc);
        __syncthreads();

        {
            int r0 = mw + g, r1 = mw + g + 8;
#pragma unroll
            for (int jn = 0; jn < 4; jn++) {
                int np = ch * 4 + jn;
                int c0 = np * 16 + 2 * tg, c1 = c0 + 8;
                float u00 = sspf(acc[jn][0][0] + s_b1[c0]);
                float u01 = sspf(acc[jn][0][1] + s_b1[c0 + 1]);
                float u10 = sspf(acc[jn][1][0] + s_b1[c1]);
                float u11 = sspf(acc[jn][1][1] + s_b1[c1 + 1]);
                float u02 = sspf(acc[jn][0][2] + s_b1[c0]);
                float u03 = sspf(acc[jn][0][3] + s_b1[c0 + 1]);
                float u12 = sspf(acc[jn][1][2] + s_b1[c1]);
                float u13 = sspf(acc[jn][1][3] + s_b1[c1 + 1]);
                *reinterpret_cast<uint32_t*>(sm + OUT_A + (uint32_t)(r0 * 272 + c0 * 2)) = pack_f16(u00, u01);
                *reinterpret_cast<uint32_t*>(sm + OUT_A + (uint32_t)(r0 * 272 + c1 * 2)) = pack_f16(u10, u11);
                *reinterpret_cast<uint32_t*>(sm + OUT_A + (uint32_t)(r1 * 272 + c0 * 2)) = pack_f16(u02, u03);
                *reinterpret_cast<uint32_t*>(sm + OUT_A + (uint32_t)(r1 * 272 + c1 * 2)) = pack_f16(u12, u13);
            }
        }
        __syncthreads();

        float acc2[4][2][4];
        hmma1f(sbase + OUT_A, sbase + OUT_B2, mw, ch * 4, lane, acc2);

        int r0 = row0 + mw + g, r1 = r0 + 8;
#pragma unroll
        for (int jn = 0; jn < 4; jn++) {
            int np = ch * 4 + jn;
            int c0 = np * 16 + 2 * tg, c1 = c0 + 8;
            if (r0 < N_ATOMS) {
                *reinterpret_cast<float2*>(out + (size_t)r0 * NF + c0) =
                    make_float2(acc2[jn][0][0] + s_b2[c0], acc2[jn][0][1] + s_b2[c0 + 1]);
                *reinterpret_cast<float2*>(out + (size_t)r0 * NF + c1) =
                    make_float2(acc2[jn][1][0] + s_b2[c1], acc2[jn][1][1] + s_b2[c1 + 1]);
            }
            if (r1 < N_ATOMS) {
                *reinterpret_cast<float2*>(out + (size_t)r1 * NF + c0) =
                    make_float2(acc2[jn][0][2] + s_b2[c0], acc2[jn][0][3] + s_b2[c0 + 1]);
                *reinterpret_cast<float2*>(out + (size_t)r1 * NF + c1) =
                    make_float2(acc2[jn][1][2] + s_b2[c1], acc2[jn][1][3] + s_b2[c1 + 1]);
            }
        }
        __syncthreads();
    }
}

// ================= launch =================
extern "C" void kernel_launch(void* const* d_in, const int* in_sizes, int n_in,
                              void* d_out, int out_size) {
    const float* x     = (const float*)d_in[0];
    const float* f_ij  = (const float*)d_in[1];
    const float* rcut  = (const float*)d_in[2];
    const float* W_in  = (const float*)d_in[3];
    const float* b_in  = (const float*)d_in[4];
    const float* Wf1   = (const float*)d_in[5];
    const float* bf1   = (const float*)d_in[6];
    const float* Wf2   = (const float*)d_in[7];
    const float* bf2   = (const float*)d_in[8];
    const float* Wo1   = (const float*)d_in[9];
    const float* bo1   = (const float*)d_in[10];
    const float* Wo2   = (const float*)d_in[11];
    const float* bo2   = (const float*)d_in[12];
    const int*   idx_i = (const int*)d_in[13];
    const int*   idx_j = (const int*)d_in[14];
    float* out = (float*)d_out;

    cudaFuncSetAttribute(k_embed, cudaFuncAttributeMaxDynamicSharedMemorySize, EMB_SMEM);
    cudaFuncSetAttribute(k_edge,  cudaFuncAttributeMaxDynamicSharedMemorySize, EDGE_SMEM);
    cudaFuncSetAttribute(k_out,   cudaFuncAttributeMaxDynamicSharedMemorySize, OUT_SMEM);

    int nsm = 148;
    cudaDeviceGetAttribute(&nsm, cudaDevAttrMultiProcessorCount, 0);

    // zero agg via async memset (graph-capturable, no alloc)
    void* aggp = nullptr;
    cudaGetSymbolAddress(&aggp, g_agg);
    cudaMemsetAsync(aggp, 0, (size_t)N_ATOMS * NF * sizeof(float));

    k_embed<<<nsm, 512, EMB_SMEM>>>(x, W_in, b_in);
    k_edge<<<nsm, 512, EDGE_SMEM>>>(f_ij, rcut, Wf1, bf1, Wf2, bf2, idx_i, idx_j);
    k_out<<<nsm, 512, OUT_SMEM>>>(Wo1, bo1, Wo2, bo2, out);
}